// round 14
// baseline (speedup 1.0000x reference)
#include <cuda_runtime.h>
#include <cuda_bf16.h>
#include <math_constants.h>

// Problem constants (from setup_inputs: x [8,4096,64] fp32, k=20)
#define B 8
#define N 4096
#define D 64
#define K 20

// Scratch (allocation-free rule: __device__ globals)
__device__ float g_sq[B * N];          // squared norms, 128 KB
__device__ int   g_nn[B * N * K];      // knn indices,   2.6 MB

// ---------------------------------------------------------------------------
// Kernel 1: squared norms per point.
// XLA *CPU* (aarch64, Neoverse V2) LLVM loop-vectorizer lowering of the
// sum(x*x,-1) reduce, D=64, fast-math (reassoc+contract): VF=4, IC=4:
//   - 16 fmla accumulator chains, chain c sums x_{16t+c}^2 for t=0..3
//     (products UNROUNDED inside fmla)
//   - interleave fold (elementwise on vec4 regs): a = (v0+v1)+(v2+v3)
//       a_c = fl( fl(ch_c + ch_{c+4}) + fl(ch_{c+8} + ch_{c+12}) )
//   - horizontal faddp pairwise: sq = fl( fl(a0+a1) + fl(a2+a3) )
// Simulated exactly per point in registers.
// ---------------------------------------------------------------------------
__global__ void sq_kernel(const float* __restrict__ x) {
    int pt = blockIdx.x * blockDim.x + threadIdx.x;
    if (pt >= B * N) return;
    const float4* xp = (const float4*)(x + (size_t)pt * D);

    float ch[16];
#pragma unroll
    for (int c = 0; c < 16; ++c) ch[c] = 0.f;

#pragma unroll
    for (int t = 0; t < 4; ++t) {
        // elements 16t .. 16t+15  (4 float4 loads)
#pragma unroll
        for (int v = 0; v < 4; ++v) {
            float4 c4 = xp[4 * t + v];
            ch[4 * v + 0] = fmaf(c4.x, c4.x, ch[4 * v + 0]);
            ch[4 * v + 1] = fmaf(c4.y, c4.y, ch[4 * v + 1]);
            ch[4 * v + 2] = fmaf(c4.z, c4.z, ch[4 * v + 2]);
            ch[4 * v + 3] = fmaf(c4.w, c4.w, ch[4 * v + 3]);
        }
    }

    // Interleave fold: (v0+v1) + (v2+v3), elementwise per lane c
    float a[4];
#pragma unroll
    for (int c = 0; c < 4; ++c) {
        a[c] = __fadd_rn(__fadd_rn(ch[c], ch[c + 4]),
                         __fadd_rn(ch[c + 8], ch[c + 12]));
    }
    // Horizontal faddp pairwise
    g_sq[pt] = __fadd_rn(__fadd_rn(a[0], a[1]), __fadd_rn(a[2], a[3]));
}

// ---------------------------------------------------------------------------
// Kernel 2: fused pairwise-distance + top-k.
// One warp per CTA, one query per thread; candidates staged in SMEM tiles of
// 32 (broadcast LDS.128 reads, conflict-free).
//
//   inner = sequential fmaf chain over d (ascending) — matches Eigen gebp /
//           fp32 sgemm per-element single-accumulator ascending-k chains
//           (products unrounded inside FMA in both).
//   dist  = __fadd_rn(__fsub_rn(sq_i, 2*inner), sq_j)  — matches the
//           ((sq[:,:,None] - 2.0*inner) + sq[:,None,:]) elementwise rounding.
// Candidates processed in ascending j; strict-< sorted insertion keeps
// equal-dist candidates in ascending-index order == lax.top_k tie-break
// (confirmed by R12: higher-index-first made tied rows WRONG).
// ---------------------------------------------------------------------------
__global__ __launch_bounds__(32) void knn_kernel(const float* __restrict__ x) {
    __shared__ float4 tile[32 * (D / 4)];   // 32 candidates x 64 dims = 8 KB
    __shared__ float  ssq[32];

    const int lane = threadIdx.x;
    const int cta  = blockIdx.x;            // 0 .. B*N/32-1
    const int b    = cta >> 7;              // N/32 = 128 CTAs per batch
    const int i    = ((cta & 127) << 5) + lane;

    const float*  xb  = x + (size_t)b * N * D;
    const float4* xb4 = (const float4*)xb;

    // Query in registers (64 floats)
    float4 q[D / 4];
    {
        const float4* xq = (const float4*)(xb + (size_t)i * D);
#pragma unroll
        for (int t = 0; t < D / 4; ++t) q[t] = xq[t];
    }
    const float sq_i = g_sq[b * N + i];

    // Top-k list, sorted ascending by (dist, index)
    float kd[K];
    int   ki[K];
#pragma unroll
    for (int t = 0; t < K; ++t) { kd[t] = CUDART_INF_F; ki[t] = 0x7fffffff; }

    const int sq_base = b * N;

    for (int jt = 0; jt < N; jt += 32) {
        // Stage 32 candidates into SMEM (coalesced float4 loads)
#pragma unroll
        for (int t = 0; t < 16; ++t) {
            int e = t * 32 + lane;                       // flat float4 index
            tile[e] = xb4[(size_t)jt * 16 + e];
        }
        ssq[lane] = g_sq[sq_base + jt + lane];
        __syncthreads();

        // 4 independent sequential FMA chains (ILP) — each chain strictly
        // ascending in d so rounding matches the reference matmul.
        for (int j0 = 0; j0 < 32; j0 += 4) {
            float a0 = 0.f, a1 = 0.f, a2 = 0.f, a3 = 0.f;
#pragma unroll
            for (int t = 0; t < D / 4; ++t) {
                float4 v0 = tile[(j0 + 0) * (D / 4) + t];
                float4 v1 = tile[(j0 + 1) * (D / 4) + t];
                float4 v2 = tile[(j0 + 2) * (D / 4) + t];
                float4 v3 = tile[(j0 + 3) * (D / 4) + t];
                a0 = fmaf(q[t].x, v0.x, a0);
                a0 = fmaf(q[t].y, v0.y, a0);
                a0 = fmaf(q[t].z, v0.z, a0);
                a0 = fmaf(q[t].w, v0.w, a0);
                a1 = fmaf(q[t].x, v1.x, a1);
                a1 = fmaf(q[t].y, v1.y, a1);
                a1 = fmaf(q[t].z, v1.z, a1);
                a1 = fmaf(q[t].w, v1.w, a1);
                a2 = fmaf(q[t].x, v2.x, a2);
                a2 = fmaf(q[t].y, v2.y, a2);
                a2 = fmaf(q[t].z, v2.z, a2);
                a2 = fmaf(q[t].w, v2.w, a2);
                a3 = fmaf(q[t].x, v3.x, a3);
                a3 = fmaf(q[t].y, v3.y, a3);
                a3 = fmaf(q[t].z, v3.z, a3);
                a3 = fmaf(q[t].w, v3.w, a3);
            }
            float dots[4] = {a0, a1, a2, a3};
#pragma unroll
            for (int m = 0; m < 4; ++m) {
                // dist = ((sq_i - 2*inner) + sq_j), exactly as jnp rounds it
                float u    = __fmul_rn(2.0f, dots[m]);   // exact (x2)
                float tt   = __fsub_rn(sq_i, u);
                float dist = __fadd_rn(tt, ssq[j0 + m]);

                if (dist < kd[K - 1]) {
                    const int jg = jt + j0 + m;
                    // stable sorted insertion (ascending index on ties)
#pragma unroll
                    for (int t = K - 1; t >= 0; --t) {
                        if (t > 0 && kd[t - 1] > dist) {
                            kd[t] = kd[t - 1];
                            ki[t] = ki[t - 1];
                        } else {
                            kd[t] = dist;
                            ki[t] = jg;
                            break;
                        }
                    }
                }
            }
        }
        __syncthreads();
    }

    int base = (b * N + i) * K;
#pragma unroll
    for (int t = 0; t < K; ++t) g_nn[base + t] = ki[t];
}

// ---------------------------------------------------------------------------
// Kernel 3: gather + edge-feature construction.
// One warp per output row (b,i,kk): 128 floats = 32 float4, one per lane.
// lane<16  -> x_target chunk ; lane>=16 -> x_neighbor - x_target chunk
// ---------------------------------------------------------------------------
__global__ void gather_kernel(const float* __restrict__ x,
                              float* __restrict__ out) {
    const int row  = (blockIdx.x * blockDim.x + threadIdx.x) >> 5;
    const int lane = threadIdx.x & 31;
    const int bi = row / K;            // b*N + i
    const int b  = bi >> 12;           // N = 4096
    const int nn = g_nn[row];

    const float4* xi = (const float4*)(x + (size_t)bi * D);
    const float4* xn = (const float4*)(x + ((size_t)(b * N + nn)) * D);

    float4 v;
    if (lane < 16) {
        v = xi[lane];
    } else {
        float4 a = xn[lane - 16];
        float4 c = xi[lane - 16];
        v = make_float4(a.x - c.x, a.y - c.y, a.z - c.z, a.w - c.w);
    }
    ((float4*)out)[(size_t)row * 32 + lane] = v;
}

// ---------------------------------------------------------------------------
extern "C" void kernel_launch(void* const* d_in, const int* in_sizes, int n_in,
                              void* d_out, int out_size) {
    const float* x   = (const float*)d_in[0];
    float*       out = (float*)d_out;

    sq_kernel<<<(B * N + 255) / 256, 256>>>(x);
    knn_kernel<<<B * N / 32, 32>>>(x);
    gather_kernel<<<(B * N * K * 32) / 256, 256>>>(x, out);
}

// round 15
// speedup vs baseline: 2.9493x; 2.9493x over previous
#include <cuda_runtime.h>
#include <cuda_bf16.h>
#include <math_constants.h>

// Problem constants (from setup_inputs: x [8,4096,64] fp32, k=20)
#define B 8
#define N 4096
#define D 64
#define K 20

// Scratch (allocation-free rule: __device__ globals)
__device__ float g_sq[B * N];          // squared norms, 128 KB
__device__ int   g_nn[B * N * K];      // knn indices,   2.6 MB

// ---------------------------------------------------------------------------
// Kernel 1: squared norms per point.  (VERIFIED bit-exact vs reference R14)
// XLA CPU LLVM loop-vectorizer lowering, VF=4 IC=4, fp-contract on:
//   16 fmla chains stride 16; fold (v0+v1)+(v2+v3) elementwise; faddp pairwise.
// ---------------------------------------------------------------------------
__global__ void sq_kernel(const float* __restrict__ x) {
    int pt = blockIdx.x * blockDim.x + threadIdx.x;
    if (pt >= B * N) return;
    const float4* xp = (const float4*)(x + (size_t)pt * D);

    float ch[16];
#pragma unroll
    for (int c = 0; c < 16; ++c) ch[c] = 0.f;

#pragma unroll
    for (int t = 0; t < 4; ++t) {
#pragma unroll
        for (int v = 0; v < 4; ++v) {
            float4 c4 = xp[4 * t + v];
            ch[4 * v + 0] = fmaf(c4.x, c4.x, ch[4 * v + 0]);
            ch[4 * v + 1] = fmaf(c4.y, c4.y, ch[4 * v + 1]);
            ch[4 * v + 2] = fmaf(c4.z, c4.z, ch[4 * v + 2]);
            ch[4 * v + 3] = fmaf(c4.w, c4.w, ch[4 * v + 3]);
        }
    }

    float a[4];
#pragma unroll
    for (int c = 0; c < 4; ++c) {
        a[c] = __fadd_rn(__fadd_rn(ch[c], ch[c + 4]),
                         __fadd_rn(ch[c + 8], ch[c + 12]));
    }
    g_sq[pt] = __fadd_rn(__fadd_rn(a[0], a[1]), __fadd_rn(a[2], a[3]));
}

// ---------------------------------------------------------------------------
// Kernel 2: fused pairwise-distance + top-k.  Arithmetic identical to R14:
//   inner = single sequential fmaf chain, d ascending (matches Eigen gebp)
//   dist  = fl(fl(sq_i - 2*inner) + sq_j)
//   ties  = stable ascending index (strict-< insertion)
// Perf changes vs R14:
//   * 8 independent candidate chains per group (ILP 8, latency hiding)
//   * branchless break-free insertion, all-static register indices
//     (prevents local-memory demotion of kd[]/ki[])
// ---------------------------------------------------------------------------
__global__ __launch_bounds__(32) void knn_kernel(const float* __restrict__ x) {
    __shared__ float4 tile[32 * (D / 4)];   // 32 candidates x 64 dims = 8 KB
    __shared__ float  ssq[32];

    const int lane = threadIdx.x;
    const int cta  = blockIdx.x;            // 0 .. B*N/32-1
    const int b    = cta >> 7;              // N/32 = 128 CTAs per batch
    const int i    = ((cta & 127) << 5) + lane;

    const float*  xb  = x + (size_t)b * N * D;
    const float4* xb4 = (const float4*)xb;

    // Query in registers (64 floats)
    float4 q[D / 4];
    {
        const float4* xq = (const float4*)(xb + (size_t)i * D);
#pragma unroll
        for (int t = 0; t < D / 4; ++t) q[t] = xq[t];
    }
    const float sq_i = g_sq[b * N + i];

    // Top-k list, sorted ascending by (dist, index)
    float kd[K];
    int   ki[K];
#pragma unroll
    for (int t = 0; t < K; ++t) { kd[t] = CUDART_INF_F; ki[t] = 0x7fffffff; }

    const int sq_base = b * N;

    for (int jt = 0; jt < N; jt += 32) {
        // Stage 32 candidates into SMEM (coalesced float4 loads)
#pragma unroll
        for (int t = 0; t < 16; ++t) {
            int e = t * 32 + lane;                       // flat float4 index
            tile[e] = xb4[(size_t)jt * 16 + e];
        }
        ssq[lane] = g_sq[sq_base + jt + lane];
        __syncthreads();

        // 8 independent sequential FMA chains (ILP) — each chain strictly
        // ascending in d so rounding matches the reference matmul.
#pragma unroll 1
        for (int j0 = 0; j0 < 32; j0 += 8) {
            float acc[8];
#pragma unroll
            for (int m = 0; m < 8; ++m) acc[m] = 0.f;

#pragma unroll
            for (int t = 0; t < D / 4; ++t) {
#pragma unroll
                for (int m = 0; m < 8; ++m) {
                    float4 v = tile[(j0 + m) * (D / 4) + t];
                    float  a = acc[m];
                    a = fmaf(q[t].x, v.x, a);
                    a = fmaf(q[t].y, v.y, a);
                    a = fmaf(q[t].z, v.z, a);
                    a = fmaf(q[t].w, v.w, a);
                    acc[m] = a;
                }
            }

#pragma unroll
            for (int m = 0; m < 8; ++m) {
                // dist = ((sq_i - 2*inner) + sq_j), exactly as jnp rounds it
                float u    = __fmul_rn(2.0f, acc[m]);    // exact (x2)
                float tt   = __fsub_rn(sq_i, u);
                float dist = __fadd_rn(tt, ssq[j0 + m]);

                if (dist < kd[K - 1]) {
                    const int jg = jt + j0 + m;
                    // Branchless shift-insert: every index static, no break.
                    // Position with kd[t] <= dist: unchanged (stable ties).
                    // First kd[t] > dist: receives (dist, jg); rest shift.
#pragma unroll
                    for (int t = K - 1; t >= 0; --t) {
                        bool cur_gt  = kd[t] > dist;
                        bool prev_gt = (t > 0) ? (kd[t - 1] > dist) : false;
                        if (cur_gt) {
                            kd[t] = prev_gt ? kd[t - 1] : dist;
                            ki[t] = prev_gt ? ki[t - 1] : jg;
                        }
                    }
                }
            }
        }
        __syncthreads();
    }

    int base = (b * N + i) * K;
#pragma unroll
    for (int t = 0; t < K; ++t) g_nn[base + t] = ki[t];
}

// ---------------------------------------------------------------------------
// Kernel 3: gather + edge-feature construction.
// One warp per output row (b,i,kk): 128 floats = 32 float4, one per lane.
// lane<16  -> x_target chunk ; lane>=16 -> x_neighbor - x_target chunk
// ---------------------------------------------------------------------------
__global__ void gather_kernel(const float* __restrict__ x,
                              float* __restrict__ out) {
    const int row  = (blockIdx.x * blockDim.x + threadIdx.x) >> 5;
    const int lane = threadIdx.x & 31;
    const int bi = row / K;            // b*N + i
    const int b  = bi >> 12;           // N = 4096
    const int nn = g_nn[row];

    const float4* xi = (const float4*)(x + (size_t)bi * D);
    const float4* xn = (const float4*)(x + ((size_t)(b * N + nn)) * D);

    float4 v;
    if (lane < 16) {
        v = xi[lane];
    } else {
        float4 a = xn[lane - 16];
        float4 c = xi[lane - 16];
        v = make_float4(a.x - c.x, a.y - c.y, a.z - c.z, a.w - c.w);
    }
    ((float4*)out)[(size_t)row * 32 + lane] = v;
}

// ---------------------------------------------------------------------------
extern "C" void kernel_launch(void* const* d_in, const int* in_sizes, int n_in,
                              void* d_out, int out_size) {
    const float* x   = (const float*)d_in[0];
    float*       out = (float*)d_out;

    sq_kernel<<<(B * N + 255) / 256, 256>>>(x);
    knn_kernel<<<B * N / 32, 32>>>(x);
    gather_kernel<<<(B * N * K * 32) / 256, 256>>>(x, out);
}

// round 16
// speedup vs baseline: 2.9504x; 1.0004x over previous
#include <cuda_runtime.h>
#include <cuda_bf16.h>
#include <math_constants.h>

// Problem constants (from setup_inputs: x [8,4096,64] fp32, k=20)
#define B 8
#define N 4096
#define D 64
#define K 20
#define NQ (B * N)
#define JHALF (N / 2)

// Scratch (allocation-free rule: __device__ globals)
__device__ float g_sq[NQ];                 // squared norms
__device__ int   g_nn[NQ * K];             // merged knn indices
__device__ float g_kd_part[2][NQ * K];     // partial top-k dists
__device__ int   g_ki_part[2][NQ * K];     // partial top-k indices

// ---------------------------------------------------------------------------
// Kernel 1: squared norms per point.  (VERIFIED bit-exact vs reference, R14)
// XLA CPU LLVM loop-vectorizer lowering, VF=4 IC=4, fp-contract on:
//   16 fmla chains stride 16; fold (v0+v1)+(v2+v3) elementwise; faddp pairwise.
// ---------------------------------------------------------------------------
__global__ void sq_kernel(const float* __restrict__ x) {
    int pt = blockIdx.x * blockDim.x + threadIdx.x;
    if (pt >= NQ) return;
    const float4* xp = (const float4*)(x + (size_t)pt * D);

    float ch[16];
#pragma unroll
    for (int c = 0; c < 16; ++c) ch[c] = 0.f;

#pragma unroll
    for (int t = 0; t < 4; ++t) {
#pragma unroll
        for (int v = 0; v < 4; ++v) {
            float4 c4 = xp[4 * t + v];
            ch[4 * v + 0] = fmaf(c4.x, c4.x, ch[4 * v + 0]);
            ch[4 * v + 1] = fmaf(c4.y, c4.y, ch[4 * v + 1]);
            ch[4 * v + 2] = fmaf(c4.z, c4.z, ch[4 * v + 2]);
            ch[4 * v + 3] = fmaf(c4.w, c4.w, ch[4 * v + 3]);
        }
    }

    float a[4];
#pragma unroll
    for (int c = 0; c < 4; ++c) {
        a[c] = __fadd_rn(__fadd_rn(ch[c], ch[c + 4]),
                         __fadd_rn(ch[c + 8], ch[c + 12]));
    }
    g_sq[pt] = __fadd_rn(__fadd_rn(a[0], a[1]), __fadd_rn(a[2], a[3]));
}

// ---------------------------------------------------------------------------
// Kernel 2: split-j partial knn.  Arithmetic bit-identical to R15:
//   inner = single sequential fmaf chain, d ascending
//   dist  = fl(fl(sq_i - 2*inner) + sq_j)
//   ties  = stable ascending index (strict-< branchless insertion)
// Each CTA (1 warp, 32 queries) scans HALF the candidate range (2048) and
// writes a sorted partial top-20.  2048 CTAs -> ~13.8 warps/SM (2x latency
// hiding vs R15's 6.9), FFMA work unchanged.
// ---------------------------------------------------------------------------
__global__ __launch_bounds__(32, 12) void knn_kernel(const float* __restrict__ x) {
    __shared__ float4 tile[32 * (D / 4)];   // 32 candidates x 64 dims = 8 KB
    __shared__ float  ssq[32];

    const int lane  = threadIdx.x;
    const int cta   = blockIdx.x;           // 0 .. 2*NQ/32 - 1
    const int half  = cta & 1;
    const int qcta  = cta >> 1;             // 0 .. NQ/32 - 1
    const int b     = qcta >> 7;            // N/32 = 128 query-CTAs per batch
    const int i     = ((qcta & 127) << 5) + lane;

    const float*  xb  = x + (size_t)b * N * D;
    const float4* xb4 = (const float4*)xb;

    // Query in registers (64 floats)
    float4 q[D / 4];
    {
        const float4* xq = (const float4*)(xb + (size_t)i * D);
#pragma unroll
        for (int t = 0; t < D / 4; ++t) q[t] = xq[t];
    }
    const float sq_i = g_sq[b * N + i];

    // Partial top-k list, sorted ascending by (dist, index)
    float kd[K];
    int   ki[K];
#pragma unroll
    for (int t = 0; t < K; ++t) { kd[t] = CUDART_INF_F; ki[t] = 0x7fffffff; }

    const int sq_base = b * N;
    const int j_lo = half * JHALF;
    const int j_hi = j_lo + JHALF;

    for (int jt = j_lo; jt < j_hi; jt += 32) {
        // Stage 32 candidates into SMEM (coalesced float4 loads)
#pragma unroll
        for (int t = 0; t < 16; ++t) {
            int e = t * 32 + lane;                       // flat float4 index
            tile[e] = xb4[(size_t)jt * 16 + e];
        }
        ssq[lane] = g_sq[sq_base + jt + lane];
        __syncthreads();

        // 8 independent sequential FMA chains (ILP) — each chain strictly
        // ascending in d so rounding matches the reference matmul.
#pragma unroll 1
        for (int j0 = 0; j0 < 32; j0 += 8) {
            float acc[8];
#pragma unroll
            for (int m = 0; m < 8; ++m) acc[m] = 0.f;

#pragma unroll
            for (int t = 0; t < D / 4; ++t) {
#pragma unroll
                for (int m = 0; m < 8; ++m) {
                    float4 v = tile[(j0 + m) * (D / 4) + t];
                    float  a = acc[m];
                    a = fmaf(q[t].x, v.x, a);
                    a = fmaf(q[t].y, v.y, a);
                    a = fmaf(q[t].z, v.z, a);
                    a = fmaf(q[t].w, v.w, a);
                    acc[m] = a;
                }
            }

#pragma unroll
            for (int m = 0; m < 8; ++m) {
                // dist = ((sq_i - 2*inner) + sq_j), exactly as jnp rounds it
                float u    = __fmul_rn(2.0f, acc[m]);    // exact (x2)
                float tt   = __fsub_rn(sq_i, u);
                float dist = __fadd_rn(tt, ssq[j0 + m]);

                if (dist < kd[K - 1]) {
                    const int jg = jt + j0 + m;
                    // Branchless shift-insert, all-static register indices.
#pragma unroll
                    for (int t = K - 1; t >= 0; --t) {
                        bool cur_gt  = kd[t] > dist;
                        bool prev_gt = (t > 0) ? (kd[t - 1] > dist) : false;
                        if (cur_gt) {
                            kd[t] = prev_gt ? kd[t - 1] : dist;
                            ki[t] = prev_gt ? ki[t - 1] : jg;
                        }
                    }
                }
            }
        }
        __syncthreads();
    }

    const int base = (b * N + i) * K;
#pragma unroll
    for (int t = 0; t < K; ++t) {
        g_kd_part[half][base + t] = kd[t];
        g_ki_part[half][base + t] = ki[t];
    }
}

// ---------------------------------------------------------------------------
// Kernel 2b: merge the two sorted partial top-20 lists per query.
// All half-0 indices < all half-1 indices, so stable ascending-index tie
// order == "pick A when kdA <= kdB".  Exact two-pointer merge.
// ---------------------------------------------------------------------------
__global__ void merge_kernel() {
    int qi = blockIdx.x * blockDim.x + threadIdx.x;
    if (qi >= NQ) return;
    const int base = qi * K;

    float akd[K], bkd[K];
    int   aki[K], bki[K];
#pragma unroll
    for (int t = 0; t < K; ++t) {
        akd[t] = g_kd_part[0][base + t];
        aki[t] = g_ki_part[0][base + t];
        bkd[t] = g_kd_part[1][base + t];
        bki[t] = g_ki_part[1][base + t];
    }

    int pa = 0, pb = 0;
#pragma unroll
    for (int t = 0; t < K; ++t) {
        // (pb can never reach K before pa exhausts picks; bounds are safe
        //  because pa<=t<K and pb<=t<K at step t)
        bool takeA = (pb >= K) || (pa < K && akd[pa] <= bkd[pb]);
        g_nn[base + t] = takeA ? aki[pa] : bki[pb];
        if (takeA) ++pa; else ++pb;
    }
}

// ---------------------------------------------------------------------------
// Kernel 3: gather + edge-feature construction.
// One warp per output row (b,i,kk): 128 floats = 32 float4, one per lane.
// lane<16  -> x_target chunk ; lane>=16 -> x_neighbor - x_target chunk
// ---------------------------------------------------------------------------
__global__ void gather_kernel(const float* __restrict__ x,
                              float* __restrict__ out) {
    const int row  = (blockIdx.x * blockDim.x + threadIdx.x) >> 5;
    const int lane = threadIdx.x & 31;
    const int bi = row / K;            // b*N + i
    const int b  = bi >> 12;           // N = 4096
    const int nn = g_nn[row];

    const float4* xi = (const float4*)(x + (size_t)bi * D);
    const float4* xn = (const float4*)(x + ((size_t)(b * N + nn)) * D);

    float4 v;
    if (lane < 16) {
        v = xi[lane];
    } else {
        float4 a = xn[lane - 16];
        float4 c = xi[lane - 16];
        v = make_float4(a.x - c.x, a.y - c.y, a.z - c.z, a.w - c.w);
    }
    ((float4*)out)[(size_t)row * 32 + lane] = v;
}

// ---------------------------------------------------------------------------
extern "C" void kernel_launch(void* const* d_in, const int* in_sizes, int n_in,
                              void* d_out, int out_size) {
    const float* x   = (const float*)d_in[0];
    float*       out = (float*)d_out;

    sq_kernel<<<(NQ + 255) / 256, 256>>>(x);
    knn_kernel<<<2 * NQ / 32, 32>>>(x);
    merge_kernel<<<(NQ + 255) / 256, 256>>>();
    gather_kernel<<<(NQ * K * 32) / 256, 256>>>(x, out);
}